// round 8
// baseline (speedup 1.0000x reference)
#include <cuda_runtime.h>
#include <cstdint>

typedef unsigned long long ull;

#define BB 512
#define TT 1024
#define IDIM 15
#define HH 64
#define ODIM 11
#define CH 16
#define NCH (TT/CH)

// scratch (static __device__ — no allocations in kernel_launch)
__device__ __align__(16) float g_xpad[(size_t)BB*TT*16];   // x padded 15 -> 16

// ---- f32x2 helpers ----
__device__ __forceinline__ ull ffma2(ull a, ull b, ull c){
    ull d; asm("fma.rn.f32x2 %0, %1, %2, %3;" : "=l"(d) : "l"(a), "l"(b), "l"(c)); return d;
}
__device__ __forceinline__ ull fadd2(ull a, ull b){
    ull d; asm("add.rn.f32x2 %0, %1, %2;" : "=l"(d) : "l"(a), "l"(b)); return d;
}
__device__ __forceinline__ ull pack2(float x, float y){
    ull r; asm("mov.b64 %0, {%1, %2};" : "=l"(r) : "f"(x), "f"(y)); return r;
}
__device__ __forceinline__ float2 unpack2(ull v){
    float2 r; asm("mov.b64 {%0, %1}, %2;" : "=f"(r.x), "=f"(r.y) : "l"(v)); return r;
}
#define BAR_ARRIVE(id) asm volatile("bar.arrive %0, 64;" :: "r"(id) : "memory")
#define BAR_SYNC(id)   asm volatile("bar.sync %0, 64;"   :: "r"(id) : "memory")

// ---- kernel 0: pad x [B,T,15] -> [B,T,16], float4 both directions via smem ----
__global__ void __launch_bounds__(256) pad_x_kernel(const float* __restrict__ x){
    __shared__ float xsm[256*IDIM];
    const int tid = threadIdx.x;
    const float4* src4 = (const float4*)(x + (size_t)blockIdx.x * (256*IDIM));
    #pragma unroll
    for (int k=0;k<4;k++){
        int idx = tid + k*256;
        if (idx < 960) ((float4*)xsm)[idx] = src4[idx];
    }
    __syncthreads();
    float4* dst4 = (float4*)(g_xpad + (size_t)blockIdx.x * (256*16));
    #pragma unroll
    for (int k=0;k<4;k++){
        int idx = tid + k*256;
        int row = idx >> 2, q = idx & 3;
        const float* rp = xsm + row*IDIM + q*4;
        float f0 = rp[0], f1 = rp[1], f2 = rp[2];
        float f3 = (q == 3) ? 0.f : rp[3];
        dst4[idx] = make_float4(f0, f1, f2, f3);
    }
}

// ---- kernel 1: warp-specialized. warps 0-3: recurrence; warps 4-7: xproj + dec ----
__global__ void __launch_bounds__(256,1) rnn_fused_kernel(
    const float* __restrict__ W_ih, const float* __restrict__ b_ih,
    const float* __restrict__ W_hh, const float* __restrict__ b_hh,
    const float* __restrict__ W_dec, const float* __restrict__ b_dec,
    float* __restrict__ out, float* __restrict__ h_out)
{
    __shared__ __align__(16) float xs[2][4][CH*16];     // raw x chunks        8KB
    __shared__ __align__(16) ull  xp[2][4][CH][32];     // xproj pairs        32KB
    __shared__ __align__(16) ull  ring[4][2][CH][32];   // h history          32KB

    const int tid = threadIdx.x;
    const int wid = tid >> 5;
    const int l   = tid & 31;

    if (wid < 4){
        // ================= RNN warp: batch b = blk*4 + wid =================
        const int b  = blockIdx.x * 4 + wid;
        const int j0 = 2*l, j1 = j0 + 1;
        const int full_bar = 2*wid + 1;
        const int free_bar = 2*wid + 2;

        ull w0[32], w1[32];
        {
            const ull* wp = (const ull*)W_hh;
            #pragma unroll
            for (int q=0;q<32;q++){ w0[q] = wp[j0*32+q]; w1[q] = wp[j1*32+q]; }
        }

        ring[wid][1][CH-1][l] = 0ULL;    // h_{-1} (read at c=0, tt=0)
        ull hlast = 0ULL;

        for (int c=0; c<NCH; c++){
            BAR_SYNC(free_bar);          // xp(c) ready & ring[c&1] free
            const ull* xpb   = &xp[c&1][wid][0][0];
            ull*       rbuf  = &ring[wid][c&1][0][0];
            const ull* hprev = &ring[wid][(c&1)^1][CH-1][0];

            #pragma unroll 4
            for (int tt=0; tt<CH; tt++){
                ull xa = xpb[tt*32 + l];                     // LDS.64
                const ulonglong2* hp = (const ulonglong2*)hprev;
                ull aa0=0ULL, aa1=0ULL, ab0=0ULL, ab1=0ULL;
                #pragma unroll
                for (int q=0;q<16;q++){
                    ulonglong2 hv = hp[q];
                    aa0 = ffma2(hv.x, w0[2*q],   aa0);
                    aa1 = ffma2(hv.x, w1[2*q],   aa1);
                    ab0 = ffma2(hv.y, w0[2*q+1], ab0);
                    ab1 = ffma2(hv.y, w1[2*q+1], ab1);
                }
                float2 s0 = unpack2(fadd2(aa0, ab0));
                float2 s1 = unpack2(fadd2(aa1, ab1));
                float2 xv = unpack2(xa);
                float h0v = fmaxf(s0.x + s0.y + xv.x, 0.f);
                float h1v = fmaxf(s1.x + s1.y + xv.y, 0.f);
                ull hpk = pack2(h0v, h1v);
                rbuf[tt*32 + l] = hpk;
                hprev = rbuf + tt*32;
                hlast = hpk;
                asm volatile("" ::: "memory");
            }
            BAR_ARRIVE(full_bar);        // ring[c&1] published
        }
        ((ull*)h_out)[b*32 + l] = hlast;

    } else {
        // ============ helper warp: xproj producer + decoder, batch p ============
        const int p  = wid - 4;
        const int b  = blockIdx.x * 4 + p;
        const int j0 = 2*l, j1 = j0 + 1;
        const int full_bar = 2*p + 1;
        const int free_bar = 2*p + 2;

        // W_ih rows j0,j1, i-paired (i=15 padded with 0)
        ull wi0[8], wi1[8];
        #pragma unroll
        for (int q=0;q<8;q++){
            float a0 = W_ih[j0*IDIM + 2*q];
            float a1 = (2*q+1 < IDIM) ? W_ih[j0*IDIM + 2*q + 1] : 0.f;
            wi0[q] = pack2(a0,a1);
            float c0 = W_ih[j1*IDIM + 2*q];
            float c1 = (2*q+1 < IDIM) ? W_ih[j1*IDIM + 2*q + 1] : 0.f;
            wi1[q] = pack2(c0,c1);
        }
        const ull bias0 = pack2(b_ih[j0]+b_hh[j0], 0.f);
        const ull bias1 = pack2(b_ih[j1]+b_hh[j1], 0.f);

        // decoder: lane l<22 -> output o=l>>1, K-half = l&1
        const int o = l >> 1;
        const bool half0 = (l & 1) == 0;
        const bool dec_store = (l < 22) && half0;
        const int hoff = half0 ? 0 : 8;   // ulonglong2 offset into h row
        ull wd[16];
        float bdec = 0.f;
        if (l < 22){
            const ull* wdp = (const ull*)W_dec;
            #pragma unroll
            for (int q=0;q<16;q++) wd[q] = wdp[o*32 + (half0?0:16) + q];
            bdec = b_dec[o];
        } else {
            #pragma unroll
            for (int q=0;q<16;q++) wd[q] = 0ULL;
        }

        const uint32_t xs_base = (uint32_t)__cvta_generic_to_shared(&xs[0][p][0]);
        const float* xsrc = g_xpad + (size_t)b * (TT*16);

        auto prefetch = [&](int c){
            if (c < NCH){
                const float* src = xsrc + (size_t)c * (CH*16);
                uint32_t dst = xs_base + (uint32_t)(c & 1) * (uint32_t)sizeof(xs[0]);
                #pragma unroll
                for (int q=0;q<2;q++){
                    int idx = q*32 + l;
                    asm volatile("cp.async.ca.shared.global [%0], [%1], 16;\n"
                        :: "r"(dst + (uint32_t)(idx*16)), "l"(src + idx*4) : "memory");
                }
            }
            asm volatile("cp.async.commit_group;\n" ::: "memory");
        };

        auto compute_xp = [&](int c){    // xproj for chunk c -> xp[c&1][p]
            const float* xb = &xs[c & 1][p][0];
            ull* dst = &xp[c & 1][p][0][0];
            #pragma unroll 4
            for (int tt=0; tt<CH; tt++){
                const ulonglong2* xv = (const ulonglong2*)(xb + tt*16);
                ull xa0 = bias0, xa1 = bias1;
                #pragma unroll
                for (int q=0;q<4;q++){
                    ulonglong2 xq = xv[q];
                    xa0 = ffma2(xq.x, wi0[2*q],   xa0);
                    xa1 = ffma2(xq.x, wi1[2*q],   xa1);
                    xa0 = ffma2(xq.y, wi0[2*q+1], xa0);
                    xa1 = ffma2(xq.y, wi1[2*q+1], xa1);
                }
                float2 s0 = unpack2(xa0), s1 = unpack2(xa1);
                dst[tt*32 + l] = pack2(s0.x + s0.y, s1.x + s1.y);
            }
        };

        // prime: chunks 0,1 in flight; xp(0) computed; signal rnn
        prefetch(0);
        prefetch(1);
        asm volatile("cp.async.wait_group 1;\n" ::: "memory");   // chunk 0 landed
        compute_xp(0);
        BAR_ARRIVE(free_bar);

        float* outp = out + (size_t)b * (TT*ODIM);

        for (int c=0; c<NCH; c++){
            prefetch(c+2);
            asm volatile("cp.async.wait_group 1;\n" ::: "memory"); // chunk c+1 landed
            BAR_SYNC(full_bar);                                     // ring[c&1] ready
            if (c+1 < NCH) compute_xp(c+1);

            // decode chunk c from the ring
            const ull* rbuf = &ring[p][c&1][0][0];
            #pragma unroll 4
            for (int s=0; s<CH; s++){
                const ulonglong2* hd = (const ulonglong2*)(rbuf + s*32 + hoff*2);
                ull d0=0ULL, d1=0ULL;
                #pragma unroll
                for (int q=0;q<8;q++){
                    ulonglong2 hv = hd[q];
                    d0 = ffma2(hv.x, wd[2*q],   d0);
                    d1 = ffma2(hv.y, wd[2*q+1], d1);
                }
                float2 ds = unpack2(fadd2(d0,d1));
                float dp = ds.x + ds.y;
                float dq = __shfl_down_sync(0xffffffffu, dp, 1);
                if (dec_store){
                    outp[(size_t)(c*CH + s)*ODIM + o] = fmaxf(dp + dq + bdec, 0.f);
                }
            }
            BAR_ARRIVE(free_bar);   // dec(c) done & xp(c+1) ready
        }
    }
}

extern "C" void kernel_launch(void* const* d_in, const int* in_sizes, int n_in,
                              void* d_out, int out_size)
{
    const float* x     = (const float*)d_in[0];
    const float* W_ih  = (const float*)d_in[1];
    const float* b_ih  = (const float*)d_in[2];
    const float* W_hh  = (const float*)d_in[3];
    const float* b_hh  = (const float*)d_in[4];
    const float* W_dec = (const float*)d_in[5];
    const float* b_dec = (const float*)d_in[6];
    float* out = (float*)d_out;

    (void)in_sizes; (void)n_in; (void)out_size;

    pad_x_kernel<<<(BB*TT)/256, 256>>>(x);
    rnn_fused_kernel<<<BB/4, 256>>>(W_ih, b_ih, W_hh, b_hh, W_dec, b_dec,
                                    out, out + (size_t)BB*TT*ODIM);
}

// round 10
// speedup vs baseline: 1.1510x; 1.1510x over previous
#include <cuda_runtime.h>
#include <cstdint>

typedef unsigned long long ull;

#define BB 512
#define TT 1024
#define IDIM 15
#define HH 64
#define ODIM 11
#define CH 16
#define NCH (TT/CH)

// scratch (static __device__ — no allocations in kernel_launch)
__device__ __align__(16) float g_xpad[(size_t)BB*TT*16];   // x padded 15 -> 16

// ---- f32x2 helpers ----
__device__ __forceinline__ ull ffma2(ull a, ull b, ull c){
    ull d; asm("fma.rn.f32x2 %0, %1, %2, %3;" : "=l"(d) : "l"(a), "l"(b), "l"(c)); return d;
}
__device__ __forceinline__ ull fadd2(ull a, ull b){
    ull d; asm("add.rn.f32x2 %0, %1, %2;" : "=l"(d) : "l"(a), "l"(b)); return d;
}
__device__ __forceinline__ ull pack2(float x, float y){
    ull r; asm("mov.b64 %0, {%1, %2};" : "=l"(r) : "f"(x), "f"(y)); return r;
}
__device__ __forceinline__ float2 unpack2(ull v){
    float2 r; asm("mov.b64 {%0, %1}, %2;" : "=f"(r.x), "=f"(r.y) : "l"(v)); return r;
}
// BSP rendezvous: BOTH warps of a batch execute bar.sync (count 64).
// No bar.arrive anywhere -> no phase-count skew, no defer-escape.
#define BAR64(id) asm volatile("bar.sync %0, 64;" :: "r"(id) : "memory")

// ---- kernel 0: pad x [B,T,15] -> [B,T,16], float4 both directions via smem ----
__global__ void __launch_bounds__(256) pad_x_kernel(const float* __restrict__ x){
    __shared__ float xsm[256*IDIM];
    const int tid = threadIdx.x;
    const float4* src4 = (const float4*)(x + (size_t)blockIdx.x * (256*IDIM));
    #pragma unroll
    for (int k=0;k<4;k++){
        int idx = tid + k*256;
        if (idx < 960) ((float4*)xsm)[idx] = src4[idx];
    }
    __syncthreads();
    float4* dst4 = (float4*)(g_xpad + (size_t)blockIdx.x * (256*16));
    #pragma unroll
    for (int k=0;k<4;k++){
        int idx = tid + k*256;
        int row = idx >> 2, q = idx & 3;
        const float* rp = xsm + row*IDIM + q*4;
        float f0 = rp[0], f1 = rp[1], f2 = rp[2];
        float f3 = (q == 3) ? 0.f : rp[3];
        dst4[idx] = make_float4(f0, f1, f2, f3);
    }
}

// ---- kernel 1: BSP warp-specialized. warps 0-3: rnn; warps 4-7: xproj + dec ----
// Interval c (between bar k=c and k=c+1):
//   rnn    : chunk c   — reads xp[c&1], writes ring[c&1]
//   helper : xp(c+1)   — writes xp[(c+1)&1]   (disjoint from rnn's read slot)
//            dec(c-1)  — reads ring[(c-1)&1]  (disjoint from rnn's write slot)
__global__ void __launch_bounds__(256,1) rnn_fused_kernel(
    const float* __restrict__ W_ih, const float* __restrict__ b_ih,
    const float* __restrict__ W_hh, const float* __restrict__ b_hh,
    const float* __restrict__ W_dec, const float* __restrict__ b_dec,
    float* __restrict__ out, float* __restrict__ h_out)
{
    __shared__ __align__(16) float xs[2][4][CH*16];     // raw x chunks        8KB
    __shared__ __align__(16) ull  xp[2][4][CH][32];     // xproj pairs        32KB
    __shared__ __align__(16) ull  ring[4][2][CH][32];   // h history          32KB

    const int tid = threadIdx.x;
    const int wid = tid >> 5;
    const int l   = tid & 31;

    if (wid < 4){
        // ================= RNN warp: batch b = blk*4 + wid =================
        const int b   = blockIdx.x * 4 + wid;
        const int j0  = 2*l, j1 = j0 + 1;
        const int bar = wid + 1;

        ull w0[32], w1[32];
        {
            const ull* wp = (const ull*)W_hh;
            #pragma unroll
            for (int q=0;q<32;q++){ w0[q] = wp[j0*32+q]; w1[q] = wp[j1*32+q]; }
        }

        ring[wid][1][CH-1][l] = 0ULL;    // h_{-1} (chunk 0 reads ring[1][CH-1])
        ull hlast = 0ULL;

        BAR64(bar);                      // S_0: xp(0) ready
        for (int c=0; c<NCH; c++){
            const ull* xpb   = &xp[c&1][wid][0][0];
            ull*       rbuf  = &ring[wid][c&1][0][0];
            const ull* hprev = &ring[wid][(c&1)^1][CH-1][0];

            #pragma unroll 4
            for (int tt=0; tt<CH; tt++){
                ull xa = xpb[tt*32 + l];                     // LDS.64
                const ulonglong2* hp = (const ulonglong2*)hprev;
                ull aa0=0ULL, aa1=0ULL, ab0=0ULL, ab1=0ULL;
                #pragma unroll
                for (int q=0;q<16;q++){
                    ulonglong2 hv = hp[q];
                    aa0 = ffma2(hv.x, w0[2*q],   aa0);
                    aa1 = ffma2(hv.x, w1[2*q],   aa1);
                    ab0 = ffma2(hv.y, w0[2*q+1], ab0);
                    ab1 = ffma2(hv.y, w1[2*q+1], ab1);
                }
                float2 s0 = unpack2(fadd2(aa0, ab0));
                float2 s1 = unpack2(fadd2(aa1, ab1));
                float2 xv = unpack2(xa);
                float h0v = fmaxf(s0.x + s0.y + xv.x, 0.f);
                float h1v = fmaxf(s1.x + s1.y + xv.y, 0.f);
                ull hpk = pack2(h0v, h1v);
                rbuf[tt*32 + l] = hpk;
                hprev = rbuf + tt*32;
                hlast = hpk;
                asm volatile("" ::: "memory");
            }
            BAR64(bar);                  // S_{c+1}: publish ring[c&1]
        }
        ((ull*)h_out)[b*32 + l] = hlast;

    } else {
        // ============ helper warp: xproj producer + decoder, batch p ============
        const int p   = wid - 4;
        const int b   = blockIdx.x * 4 + p;
        const int j0  = 2*l, j1 = j0 + 1;
        const int bar = p + 1;

        // W_ih rows j0,j1, i-paired (i=15 padded with 0)
        ull wi0[8], wi1[8];
        #pragma unroll
        for (int q=0;q<8;q++){
            float a0 = W_ih[j0*IDIM + 2*q];
            float a1 = (2*q+1 < IDIM) ? W_ih[j0*IDIM + 2*q + 1] : 0.f;
            wi0[q] = pack2(a0,a1);
            float c0 = W_ih[j1*IDIM + 2*q];
            float c1 = (2*q+1 < IDIM) ? W_ih[j1*IDIM + 2*q + 1] : 0.f;
            wi1[q] = pack2(c0,c1);
        }
        const ull bias0 = pack2(b_ih[j0]+b_hh[j0], 0.f);
        const ull bias1 = pack2(b_ih[j1]+b_hh[j1], 0.f);

        // decoder: lane l<22 -> output o=l>>1, K-half = l&1
        const int o = l >> 1;
        const bool half0 = (l & 1) == 0;
        const bool dec_store = (l < 22) && half0;
        const int hoff = half0 ? 0 : 8;   // ulonglong2 offset into h row
        ull wd[16];
        float bdec = 0.f;
        if (l < 22){
            const ull* wdp = (const ull*)W_dec;
            #pragma unroll
            for (int q=0;q<16;q++) wd[q] = wdp[o*32 + (half0?0:16) + q];
            bdec = b_dec[o];
        } else {
            #pragma unroll
            for (int q=0;q<16;q++) wd[q] = 0ULL;
        }

        const uint32_t xs_base = (uint32_t)__cvta_generic_to_shared(&xs[0][p][0]);
        const float* xsrc = g_xpad + (size_t)b * (TT*16);

        auto prefetch = [&](int c){
            if (c < NCH){
                const float* src = xsrc + (size_t)c * (CH*16);
                uint32_t dst = xs_base + (uint32_t)(c & 1) * (uint32_t)sizeof(xs[0]);
                #pragma unroll
                for (int q=0;q<2;q++){
                    int idx = q*32 + l;
                    asm volatile("cp.async.ca.shared.global [%0], [%1], 16;\n"
                        :: "r"(dst + (uint32_t)(idx*16)), "l"(src + idx*4) : "memory");
                }
            }
            asm volatile("cp.async.commit_group;\n" ::: "memory");
        };

        auto compute_xp = [&](int c){    // xproj for chunk c -> xp[c&1][p]
            const float* xb = &xs[c & 1][p][0];
            ull* dst = &xp[c & 1][p][0][0];
            #pragma unroll 4
            for (int tt=0; tt<CH; tt++){
                const ulonglong2* xv = (const ulonglong2*)(xb + tt*16);
                ull xa0 = bias0, xa1 = bias1;
                #pragma unroll
                for (int q=0;q<4;q++){
                    ulonglong2 xq = xv[q];
                    xa0 = ffma2(xq.x, wi0[2*q],   xa0);
                    xa1 = ffma2(xq.x, wi1[2*q],   xa1);
                    xa0 = ffma2(xq.y, wi0[2*q+1], xa0);
                    xa1 = ffma2(xq.y, wi1[2*q+1], xa1);
                }
                float2 s0 = unpack2(xa0), s1 = unpack2(xa1);
                dst[tt*32 + l] = pack2(s0.x + s0.y, s1.x + s1.y);
            }
        };

        auto dec_chunk = [&](int c, float* outp){  // decode ring[c&1] -> out
            const ull* rbuf = &ring[p][c&1][0][0];
            #pragma unroll 4
            for (int s=0; s<CH; s++){
                const ulonglong2* hd = (const ulonglong2*)(rbuf + s*32 + hoff*2);
                ull d0=0ULL, d1=0ULL;
                #pragma unroll
                for (int q=0;q<8;q++){
                    ulonglong2 hv = hd[q];
                    d0 = ffma2(hv.x, wd[2*q],   d0);
                    d1 = ffma2(hv.y, wd[2*q+1], d1);
                }
                float2 ds = unpack2(fadd2(d0,d1));
                float dp = ds.x + ds.y;
                float dq = __shfl_down_sync(0xffffffffu, dp, 1);
                if (dec_store){
                    outp[(size_t)(c*CH + s)*ODIM + o] = fmaxf(dp + dq + bdec, 0.f);
                }
            }
        };

        float* outp = out + (size_t)b * (TT*ODIM);

        // prime: chunks 0,1 in flight; xp(0) built
        prefetch(0);
        prefetch(1);
        asm volatile("cp.async.wait_group 1;\n" ::: "memory");   // chunk 0 landed
        compute_xp(0);
        BAR64(bar);                      // S_0: xp(0) published

        for (int c=0; c<NCH; c++){
            // build xp(c+1) while rnn runs chunk c
            if (c+1 < NCH){
                prefetch(c+2);
                asm volatile("cp.async.wait_group 1;\n" ::: "memory"); // chunk c+1 landed
                compute_xp(c+1);
            }
            // decode previous chunk (ring[(c-1)&1]; rnn is writing ring[c&1])
            if (c > 0) dec_chunk(c-1, outp);
            BAR64(bar);                  // S_{c+1}
        }
        // after final barrier: rnn done; decode last chunk
        dec_chunk(NCH-1, outp);
    }
}

extern "C" void kernel_launch(void* const* d_in, const int* in_sizes, int n_in,
                              void* d_out, int out_size)
{
    const float* x     = (const float*)d_in[0];
    const float* W_ih  = (const float*)d_in[1];
    const float* b_ih  = (const float*)d_in[2];
    const float* W_hh  = (const float*)d_in[3];
    const float* b_hh  = (const float*)d_in[4];
    const float* W_dec = (const float*)d_in[5];
    const float* b_dec = (const float*)d_in[6];
    float* out = (float*)d_out;

    (void)in_sizes; (void)n_in; (void)out_size;

    pad_x_kernel<<<(BB*TT)/256, 256>>>(x);
    rnn_fused_kernel<<<BB/4, 256>>>(W_ih, b_ih, W_hh, b_hh, W_dec, b_dec,
                                    out, out + (size_t)BB*TT*ODIM);
}